// round 5
// baseline (speedup 1.0000x reference)
#include <cuda_runtime.h>
#include <math.h>

#define BB 64
#define TMAX 256
#define PP 64
#define DD 128
#define CC 10
#define TBASE 367

// Scratch (no cudaMalloc allowed)
__device__ int    d_len[BB];
__device__ int    d_off[BB + 1];
__device__ float  d_E[TBASE * CC];            // E[date*C + c]
__device__ float4 d_Y4[BB * CC * (PP / 4)];   // Y[b][c][p] as float4 along p

// k_setup role partition
#define NB_Y    512                 // blocks 0..511: Y (8 warps, one (b,p) per warp)
#define NB_E    92                  // blocks 512..603: E (4 dates per block)
#define BID_LEN (NB_Y + NB_E)       // block 604: lengths + prefix sum
#define NB_SETUP (BID_LEN + 1)

// ---------------------------------------------------------------------------
// Fused setup kernel: Y precompute + E table + ragged lengths/offsets.
// ---------------------------------------------------------------------------
__global__ void __launch_bounds__(256) k_setup(const float* __restrict__ x,
                                               const int*   __restrict__ dates,
                                               const float* __restrict__ W,
                                               const float* __restrict__ bias) {
    int bid = blockIdx.x;
    int tid = threadIdx.x;

    if (bid < NB_Y) {
        // ---- Y[b][c][p] = bias[c] + x[b,p,:] . W[c,:]  (one warp per (b,p))
        int w    = bid * 8 + (tid >> 5);
        int lane = tid & 31;
        int b = w / PP;
        int p = w % PP;

        const float4* x4 = (const float4*)x;
        float4 xv = x4[(size_t)(b * PP + p) * (DD / 4) + lane];
        const float4* W4 = (const float4*)W;
        float* Yf = (float*)d_Y4;

        #pragma unroll
        for (int c = 0; c < CC; ++c) {
            float4 wv = W4[c * (DD / 4) + lane];
            float v = fmaf(xv.x, wv.x, fmaf(xv.y, wv.y, fmaf(xv.z, wv.z, xv.w * wv.w)));
            #pragma unroll
            for (int o = 16; o > 0; o >>= 1)
                v += __shfl_down_sync(0xffffffffu, v, o);
            if (lane == 0)
                Yf[(b * CC + c) * PP + p] = v + bias[c];
        }
    } else if (bid < BID_LEN) {
        // ---- E[pos,c] = sinusoid_table[pos,:] . W[c,:]
        // 4 dates per block; 64 threads per date, one (sin,cos) pair each.
        __shared__ double s_if[64];           // inv_freq[k] = TBASE^(-2k/D)
        __shared__ float  s_part[4][CC][2];

        if (tid < 64)
            s_if[tid] = pow((double)TBASE, -2.0 * (double)tid / (double)DD);
        __syncthreads();

        int sub = tid >> 6;           // 0..3: date within block
        int k   = tid & 63;           // 0..63: frequency index (j = 2k, 2k+1)
        int pos = (bid - NB_Y) * 4 + sub;

        double sv = 0.0, cv = 0.0;
        if (pos < TBASE)
            sincos((double)pos * s_if[k], &sv, &cv);
        float s  = (float)sv;
        float co = (float)cv;

        #pragma unroll
        for (int c = 0; c < CC; ++c) {
            float v = fmaf(s, W[c * DD + 2 * k], co * W[c * DD + 2 * k + 1]);
            #pragma unroll
            for (int o = 16; o > 0; o >>= 1)
                v += __shfl_down_sync(0xffffffffu, v, o);
            if ((tid & 31) == 0)
                s_part[sub][c][(tid >> 5) & 1] = v;
        }
        __syncthreads();
        if (k < CC && pos < TBASE)
            d_E[pos * CC + k] = s_part[sub][k][0] + s_part[sub][k][1];
    } else {
        // ---- lengths: last-nonzero index per row, then exclusive prefix sum
        __shared__ int s_len[BB];
        int b = tid >> 2;            // 4 threads per row
        int k = tid & 3;
        const int4* row4 = (const int4*)(dates + b * TMAX);
        int last = -1;
        #pragma unroll
        for (int i = 0; i < 16; ++i) {
            int idx = k + i * 4;     // int4 index (i ascending => keep max)
            int4 v = row4[idx];
            int bt = idx * 4;
            if (v.x != 0) last = bt;
            if (v.y != 0) last = bt + 1;
            if (v.z != 0) last = bt + 2;
            if (v.w != 0) last = bt + 3;
        }
        last = max(last, __shfl_down_sync(0xffffffffu, last, 2, 4));
        last = max(last, __shfl_down_sync(0xffffffffu, last, 1, 4));
        if (k == 0) {
            int L = (last < 0) ? (TMAX - 1) : last;
            s_len[b] = L;
            d_len[b] = L;
        }
        __syncthreads();
        if (tid == 0) {
            int acc = 0;
            #pragma unroll
            for (int i = 0; i < BB; ++i) { d_off[i] = acc; acc += s_len[i]; }
            d_off[BB] = acc;
        }
    }
}

// ---------------------------------------------------------------------------
// Write kernel: grid (TMAX/TCHUNK, B), 320 threads (2 token slots x 160).
// Stage all 160 e-values for the chunk into shared in one gather pass, then
// each thread prefetches its 8 e's to registers and issues 8 dependence-free
// STG.128.
// ---------------------------------------------------------------------------
#define TCHUNK 16

__global__ void __launch_bounds__(320) k_write(const int* __restrict__ dates,
                                               float* __restrict__ out) {
    __shared__ float s_e[TCHUNK][CC];
    int b  = blockIdx.y;
    int t0 = blockIdx.x * TCHUNK;

    int L = d_len[b];
    if (t0 >= L) return;     // uniform per block

    int tid  = threadIdx.x;              // 0..319
    int n0   = d_off[b];
    int Ntot = d_off[BB];

    if (tid < TCHUNK * CC) {             // 160 threads: one (token, c) each
        int tt = tid / CC;
        int cc = tid - tt * CC;
        int date = __ldg(&dates[b * TMAX + t0 + tt]);
        s_e[tt][cc] = __ldg(&d_E[date * CC + cc]);
    }
    __syncthreads();

    int slot = tid >= 160 ? 1 : 0;       // token parity slot
    int r    = tid - slot * 160;         // 0..159
    int c    = r >> 4;                   // 0..9
    int p4   = r & 15;                   // 0..15

    float4 y = d_Y4[(b * CC + c) * (PP / 4) + p4];

    float e[TCHUNK / 2];
    #pragma unroll
    for (int i = 0; i < TCHUNK / 2; ++i)
        e[i] = s_e[2 * i + slot][c];

    float4* out4 = (float4*)out;
    size_t mask_base = (size_t)Ntot * (CC * PP);

    #pragma unroll
    for (int i = 0; i < TCHUNK / 2; ++i) {
        int t = t0 + 2 * i + slot;
        if (t >= L) break;               // t ascending in i for fixed slot
        int n = n0 + t;
        out4[(size_t)n * 160 + r] =
            make_float4(y.x + e[i], y.y + e[i], y.z + e[i], y.w + e[i]);
        if (r < 2)
            out[mask_base + (size_t)n * 2 + r] = (r == 0) ? (float)b : (float)t;
    }
}

// ---------------------------------------------------------------------------
extern "C" void kernel_launch(void* const* d_in, const int* in_sizes, int n_in,
                              void* d_out, int out_size) {
    const float* x     = (const float*)d_in[0];
    // d_in[1] = attentions (unused by the reference computation)
    const int*   dates = (const int*)d_in[2];
    const float* W     = (const float*)d_in[3];
    const float* bias  = (const float*)d_in[4];
    float* out = (float*)d_out;

    k_setup<<<NB_SETUP, 256>>>(x, dates, W, bias);

    dim3 grid(TMAX / TCHUNK, BB);
    k_write<<<grid, 320>>>(dates, out);
}